// round 1
// baseline (speedup 1.0000x reference)
#include <cuda_runtime.h>
#include <cuda_bf16.h>
#include <math.h>

// Shapes: x (4,8,256,64,64) f32; w_k/w_q/w_v (128,256,3,3); w_out (256,128,3,3); b_out (256)
// out (4,8,256,64,64) f32
//
// Scratch (device globals; no runtime allocation):
//   g_k      (4,128,64,64)
//   g_q      (32,128,64,64)   [frame-major: b*8+t]
//   g_v      (32,128,64,64)
//   g_pooled (4,128,64,64)

#define HWPIX 4096  // 64*64

__device__ float g_scratch[(4 + 32 + 32 + 4) * 128 * HWPIX];

// ---------------------------------------------------------------------------
// Implicit-GEMM 3x3 conv, pad=1, 64x64 images.
// Block tile: 32 output channels x 4 rows x 64 cols. 256 threads.
// Thread: 8 oc x 4 rows x 1 col  (32 accumulators).
// Channel chunk: 8. smem: input 8x6x66 (12.7KB) + weights 32x8x9 (9.2KB).
// ---------------------------------------------------------------------------
template <int CIN>
__global__ __launch_bounds__(256) void conv3x3_kernel(
    const float* __restrict__ in, long inBatchStride,
    const float* __restrict__ w,
    const float* __restrict__ bias,
    float* __restrict__ out, long outBatchStride,
    int repl, long replStride)
{
    __shared__ float s_in[8][6][66];
    __shared__ float s_w[32][8][9];

    const int n   = blockIdx.z;
    const int oc0 = blockIdx.y * 32;
    const int r0  = blockIdx.x * 4;
    const int tid = threadIdx.x;
    const int col = tid & 63;
    const int og  = tid >> 6;   // 0..3  (8 output channels each)

    const float* inN = in + (long)n * inBatchStride;

    float acc[8][4];
#pragma unroll
    for (int j = 0; j < 8; j++)
#pragma unroll
        for (int r = 0; r < 4; r++) acc[j][r] = 0.f;

    for (int c0 = 0; c0 < CIN; c0 += 8) {
        __syncthreads();
        // ---- load input tile: 8 channels x 6 rows x 66 cols (zero-padded) ----
        for (int idx = tid; idx < 8 * 6 * 66; idx += 256) {
            int c   = idx / 396;
            int rem = idx - c * 396;
            int row = rem / 66;
            int cp  = rem - row * 66;
            int gr  = r0 - 1 + row;
            int gc  = cp - 1;
            float v = 0.f;
            if (gr >= 0 && gr < 64 && gc >= 0 && gc < 64)
                v = inN[(long)(c0 + c) * HWPIX + gr * 64 + gc];
            s_in[c][row][cp] = v;
        }
        // ---- load weight tile: 32 oc x 8 ic x 9 ----
        for (int idx = tid; idx < 32 * 8 * 9; idx += 256) {
            int o   = idx / 72;
            int rem = idx - o * 72;
            int c   = rem / 9;
            int k9  = rem - c * 9;
            s_w[o][c][k9] = w[((long)(oc0 + o) * CIN + (c0 + c)) * 9 + k9];
        }
        __syncthreads();

#pragma unroll
        for (int c = 0; c < 8; c++) {
            // cache the 6x3 input window for this thread's column
            float xall[6][3];
#pragma unroll
            for (int rr = 0; rr < 6; rr++)
#pragma unroll
                for (int dx = 0; dx < 3; dx++)
                    xall[rr][dx] = s_in[c][rr][col + dx];

#pragma unroll
            for (int dy = 0; dy < 3; dy++) {
#pragma unroll
                for (int dx = 0; dx < 3; dx++) {
#pragma unroll
                    for (int j = 0; j < 8; j++) {
                        float wv = s_w[og * 8 + j][c][dy * 3 + dx];
#pragma unroll
                        for (int r = 0; r < 4; r++)
                            acc[j][r] += wv * xall[r + dy][dx];
                    }
                }
            }
        }
    }

    // ---- store (optionally + bias, optionally replicated over T) ----
#pragma unroll
    for (int j = 0; j < 8; j++) {
        int o   = oc0 + og * 8 + j;
        float b = bias ? bias[o] : 0.f;
#pragma unroll
        for (int r = 0; r < 4; r++) {
            float v   = acc[j][r] + b;
            long base = (long)n * outBatchStride + (long)o * HWPIX + (r0 + r) * 64 + col;
            for (int t = 0; t < repl; t++)
                out[base + (long)t * replStride] = v;
        }
    }
}

// ---------------------------------------------------------------------------
// Per-pixel attention: dots over DH=128, softmax over T=8, pool v.
// q,v: (32,128,4096) frame-major; k,pooled: (4,128,4096)
// ---------------------------------------------------------------------------
__global__ __launch_bounds__(256) void attn_kernel(
    const float* __restrict__ q, const float* __restrict__ k,
    const float* __restrict__ v, float* __restrict__ pooled)
{
    const int pix = blockIdx.x * blockDim.x + threadIdx.x;  // 0..4095
    const int b   = blockIdx.y;

    const float* qb = q + (long)b * 8 * 128 * HWPIX;
    const float* kb = k + (long)b * 128 * HWPIX;
    const float* vb = v + (long)b * 8 * 128 * HWPIX;

    float dots[8];
#pragma unroll
    for (int t = 0; t < 8; t++) dots[t] = 0.f;

    for (int c = 0; c < 128; c++) {
        float kv = kb[c * HWPIX + pix];
#pragma unroll
        for (int t = 0; t < 8; t++)
            dots[t] += qb[((long)t * 128 + c) * HWPIX + pix] * kv;
    }

    float m = dots[0];
#pragma unroll
    for (int t = 1; t < 8; t++) m = fmaxf(m, dots[t]);
    float a[8];
    float s = 0.f;
#pragma unroll
    for (int t = 0; t < 8; t++) { a[t] = expf(dots[t] - m); s += a[t]; }
    float inv = 1.f / s;
#pragma unroll
    for (int t = 0; t < 8; t++) a[t] *= inv;

    for (int c = 0; c < 128; c++) {
        float accv = 0.f;
#pragma unroll
        for (int t = 0; t < 8; t++)
            accv += a[t] * vb[((long)t * 128 + c) * HWPIX + pix];
        pooled[(long)b * 128 * HWPIX + c * HWPIX + pix] = accv;
    }
}

// ---------------------------------------------------------------------------

extern "C" void kernel_launch(void* const* d_in, const int* in_sizes, int n_in,
                              void* d_out, int out_size)
{
    const float* x     = (const float*)d_in[0];
    const float* w_k   = (const float*)d_in[1];
    const float* w_q   = (const float*)d_in[2];
    const float* w_v   = (const float*)d_in[3];
    const float* w_out = (const float*)d_in[4];
    const float* b_out = (const float*)d_in[5];
    float* out = (float*)d_out;

    void* basev = nullptr;
    cudaGetSymbolAddress(&basev, g_scratch);
    float* gk = (float*)basev;                 // 4*128*4096
    float* gq = gk + (long)4  * 128 * HWPIX;   // 32*128*4096
    float* gv = gq + (long)32 * 128 * HWPIX;   // 32*128*4096
    float* gp = gv + (long)32 * 128 * HWPIX;   // 4*128*4096

    const long CHW   = (long)256 * HWPIX;        // per-frame x stride
    const long TCHW  = (long)8 * CHW;            // per-batch x stride
    const long DHW   = (long)128 * HWPIX;

    // k = conv(x[:,0], w_k): N=4 images, batch stride skips T
    conv3x3_kernel<256><<<dim3(16, 128 / 32, 4), 256>>>(
        x, TCHW, w_k, nullptr, gk, DHW, 1, 0);

    // q = conv(all 32 frames, w_q)
    conv3x3_kernel<256><<<dim3(16, 128 / 32, 32), 256>>>(
        x, CHW, w_q, nullptr, gq, DHW, 1, 0);

    // v = conv(all 32 frames, w_v)
    conv3x3_kernel<256><<<dim3(16, 128 / 32, 32), 256>>>(
        x, CHW, w_v, nullptr, gv, DHW, 1, 0);

    // attention + pooling
    attn_kernel<<<dim3(HWPIX / 256, 4), 256>>>(gq, gk, gv, gp);

    // out conv + bias, broadcast over T=8
    conv3x3_kernel<128><<<dim3(16, 256 / 32, 4), 256>>>(
        gp, DHW, w_out, b_out, out, TCHW, 8, CHW);
}